// round 13
// baseline (speedup 1.0000x reference)
#include <cuda_runtime.h>
#include <cuda_fp16.h>
#include <cstdint>

// ------------- problem constants -------------
#define CIN   128
#define COUT  256
#define HIN   56
#define WIN   56
#define HOUT  54
#define WOUT  54
#define NPIX  (HOUT*WOUT)
#define BATCH 64
#define TPI   729                 // 27x27 winograd tiles per image
#define NTILES (BATCH*TPI)        // 46656
#define NW    (COUT*CIN*9)

// GEMM smem: 2 stages x 2 pos x (A 64x272B + B 128x272B)
#define ROWB  272
#define A_SM  (64*ROWB)           // 17408
#define B_SM  (128*ROWB)          // 34816
#define SUB   (A_SM + B_SM)       // 52224 per pos
#define STG2  (2*SUB)             // per stage (2 pos)
#define EPS   65                  // epilogue float4 stride
#define SM_TOTAL (2*STG2)         // 208896

// fused x-transform smem: strip [4][56][130] halves + out staging [2][16][128]
#define XT_STRIP (4*56*130)       // halves
#define XT_SM (XT_STRIP*2 + 2*16*128*2)   // 58240 + 8192 = 66432

// ------------- device scratch -------------
__device__ int g_max_bits = 0;    // idempotent across replays (same inputs)
__device__ __align__(256) __half g_V[(size_t)NTILES*16*CIN];   // [tile][pos][ci]
__device__ __align__(256) __half g_wu[16*COUT*CIN];            // [pos][co][ci]

// ------------- helpers -------------
__device__ __forceinline__ uint32_t smem_u32(const void* p) {
    uint32_t a;
    asm("{ .reg .u64 t; cvta.to.shared.u64 t, %1; cvt.u32.u64 %0, t; }"
        : "=r"(a) : "l"(p));
    return a;
}
__device__ __forceinline__ void cpa16(uint32_t dst, const void* src) {
    asm volatile("cp.async.cg.shared.global [%0], [%1], 16;"
                 :: "r"(dst), "l"(src) : "memory");
}
__device__ __forceinline__ void cpa_commit() {
    asm volatile("cp.async.commit_group;" ::: "memory");
}
template <int N>
__device__ __forceinline__ void cpa_wait() {
    asm volatile("cp.async.wait_group %0;" :: "n"(N) : "memory");
}
__device__ __forceinline__ void ldsm4(uint32_t* r, uint32_t a) {
    asm volatile("ldmatrix.sync.aligned.m8n8.x4.shared.b16 {%0,%1,%2,%3}, [%4];"
                 : "=r"(r[0]), "=r"(r[1]), "=r"(r[2]), "=r"(r[3]) : "r"(a));
}
__device__ __forceinline__ void mma16816(float* d, const uint32_t* a, const uint32_t* b) {
    asm volatile(
        "mma.sync.aligned.m16n8k16.row.col.f32.f16.f16.f32 "
        "{%0,%1,%2,%3}, {%4,%5,%6,%7}, {%8,%9}, {%0,%1,%2,%3};"
        : "+f"(d[0]), "+f"(d[1]), "+f"(d[2]), "+f"(d[3])
        : "r"(a[0]), "r"(a[1]), "r"(a[2]), "r"(a[3]), "r"(b[0]), "r"(b[1]));
}

// ---------------- kernel 1: max |w| ----------------
__global__ void maxabs_kernel(const float* __restrict__ w, int n) {
    float m = 0.f;
    for (int i = blockIdx.x * blockDim.x + threadIdx.x; i < n; i += gridDim.x * blockDim.x)
        m = fmaxf(m, fabsf(w[i]));
#pragma unroll
    for (int o = 16; o; o >>= 1) m = fmaxf(m, __shfl_xor_sync(0xffffffffu, m, o));
    __shared__ float sm[8];
    int lane = threadIdx.x & 31, wid = threadIdx.x >> 5;
    if (lane == 0) sm[wid] = m;
    __syncthreads();
    if (wid == 0) {
        m = (lane < 8) ? sm[lane] : 0.f;
#pragma unroll
        for (int o = 4; o; o >>= 1) m = fmaxf(m, __shfl_xor_sync(0xffffffffu, m, o));
        if (lane == 0) atomicMax(&g_max_bits, __float_as_int(m));
    }
}

// ---------------- kernel 2: quantize + winograd weight transform ----------------
__global__ void __launch_bounds__(128)
wtrans_kernel(const float* __restrict__ w,
              const float* __restrict__ wp,
              const float* __restrict__ wn) {
    __shared__ __align__(16) __half stg[16][128];
    const int co = blockIdx.x, ci = threadIdx.x;
    const float t   = 0.05f * __int_as_float(g_max_bits);
    const float wpa = fabsf(wp[0]);
    const float wna = fabsf(wn[0]);
    const float* g = w + ((size_t)co * CIN + ci) * 9;
    float q[9];
#pragma unroll
    for (int k = 0; k < 9; ++k) {
        float v = g[k];
        q[k] = (v > t) ? wpa : ((v < -t) ? -wna : 0.f);
    }
    float T[4][3];
#pragma unroll
    for (int c = 0; c < 3; ++c) {
        T[0][c] = q[c];
        T[1][c] = 0.5f * (q[c] + q[3 + c] + q[6 + c]);
        T[2][c] = 0.5f * (q[c] - q[3 + c] + q[6 + c]);
        T[3][c] = q[6 + c];
    }
#pragma unroll
    for (int r = 0; r < 4; ++r) {
        float u0 = T[r][0];
        float u1 = 0.5f * (T[r][0] + T[r][1] + T[r][2]);
        float u2 = 0.5f * (T[r][0] - T[r][1] + T[r][2]);
        float u3 = T[r][2];
        stg[r * 4 + 0][ci] = __float2half_rn(u0);
        stg[r * 4 + 1][ci] = __float2half_rn(u1);
        stg[r * 4 + 2][ci] = __float2half_rn(u2);
        stg[r * 4 + 3][ci] = __float2half_rn(u3);
    }
    __syncthreads();
#pragma unroll
    for (int k = 0; k < 2; ++k) {
        int chunk = k * 128 + threadIdx.x;
        int pos = chunk >> 4, off = chunk & 15;
        ((uint4*)(g_wu + ((size_t)(pos * COUT + co)) * CIN))[off] =
            ((const uint4*)&stg[pos][0])[off];
    }
}

// ---------------- kernel 3: fused NCHW f32 -> winograd V (fp16), staged stores ----------------
__global__ void __launch_bounds__(256)
xtrans_kernel(const float* __restrict__ x) {
    extern __shared__ __half smh[];       // strip [4][56][130], then stgout [2][16][128]
    __half* stgout = smh + XT_STRIP;
    const int b  = blockIdx.x / 27;
    const int ty = blockIdx.x % 27;
    const float* src = x + (size_t)b * CIN * HIN * WIN + (2 * ty) * WIN;

    // load 4-row strip, all channels: smh[yy][xx][ci]
    for (int i = threadIdx.x; i < CIN * 4 * WIN; i += 256) {
        int ci  = i / (4 * WIN);
        int rem = i - ci * (4 * WIN);
        int yy  = rem / WIN;
        int xx  = rem - yy * WIN;
        smh[(yy * WIN + xx) * 130 + ci] =
            __float2half_rn(src[(size_t)ci * (HIN * WIN) + yy * WIN + xx]);
    }
    __syncthreads();

    const int tl = threadIdx.x >> 7, ci = threadIdx.x & 127;
    const size_t tile_base = ((size_t)(b * TPI + ty * 27)) * 16 * CIN;
#pragma unroll 1
    for (int i2 = 0; i2 < 14; ++i2) {
        const int tx = i2 * 2 + tl;
        if (tx < 27) {
            float d[4][4];
#pragma unroll
            for (int yy = 0; yy < 4; ++yy)
#pragma unroll
                for (int xx = 0; xx < 4; ++xx)
                    d[yy][xx] = __half2float(smh[(yy * WIN + 2 * tx + xx) * 130 + ci]);
            float tm[4][4];
#pragma unroll
            for (int c = 0; c < 4; ++c) {
                tm[0][c] = d[0][c] - d[2][c];
                tm[1][c] = d[1][c] + d[2][c];
                tm[2][c] = d[2][c] - d[1][c];
                tm[3][c] = d[1][c] - d[3][c];
            }
            __half* so = stgout + tl * (16 * 128) + ci;
#pragma unroll
            for (int rr = 0; rr < 4; ++rr) {
                so[(rr * 4 + 0) * 128] = __float2half_rn(tm[rr][0] - tm[rr][2]);
                so[(rr * 4 + 1) * 128] = __float2half_rn(tm[rr][1] + tm[rr][2]);
                so[(rr * 4 + 2) * 128] = __float2half_rn(tm[rr][2] - tm[rr][1]);
                so[(rr * 4 + 3) * 128] = __float2half_rn(tm[rr][1] - tm[rr][3]);
            }
        }
        __syncthreads();
        // staged copy: 512 uint4 (2 tiles x 16 pos x 16B), fully coalesced
#pragma unroll
        for (int k = 0; k < 2; ++k) {
            const int id = k * 256 + threadIdx.x;
            const int tloc = id >> 8;
            const int rem  = id & 255;
            const int txx  = i2 * 2 + tloc;
            if (txx < 27)
                ((uint4*)(g_V + tile_base + (size_t)txx * 16 * CIN))[rem] =
                    ((const uint4*)stgout)[id];
        }
        __syncthreads();
    }
}

// ---------------- output-transform accumulate ----------------
__device__ __forceinline__ void wg_accum(int pos, const float (&f)[2][4][4],
                                         float (&oacc)[2][4][4][4]) {
    const int p = pos >> 2, q = pos & 3;
    const float cp0 = (p == 3) ? 0.f : 1.f;
    const float cp1 = (p == 0) ? 0.f : ((p == 1) ? 1.f : -1.f);
    const float cq0 = (q == 3) ? 0.f : 1.f;
    const float cq1 = (q == 0) ? 0.f : ((q == 1) ? 1.f : -1.f);
    const float w00 = cp0 * cq0, w01 = cp0 * cq1;
    const float w10 = cp1 * cq0, w11 = cp1 * cq1;
#pragma unroll
    for (int mf = 0; mf < 2; ++mf)
#pragma unroll
        for (int nf = 0; nf < 4; ++nf)
#pragma unroll
            for (int e = 0; e < 4; ++e) {
                const float v = f[mf][nf][e];
                oacc[mf][nf][e][0] += w00 * v;
                oacc[mf][nf][e][1] += w01 * v;
                oacc[mf][nf][e][2] += w10 * v;
                oacc[mf][nf][e][3] += w11 * v;
            }
}

// ---------------- kernel 4: winograd GEMM, pos-pair interleaved ----------------
__global__ void __launch_bounds__(256, 1)
wg_gemm_kernel(const float* __restrict__ bias, float* __restrict__ out) {
    extern __shared__ char smem[];
    const uint32_t sb = smem_u32(smem);
    const int tid = threadIdx.x;
    const int wid = tid >> 5, lane = tid & 31;
    const int n0  = blockIdx.x * 128;      // cout base (FAST axis -> A L2 reuse)
    const int m0t = blockIdx.y * 64;       // tile base

    // warp grid 2(m) x 4(n); warp tile 32(m) x 32(n)
    const int wm = (wid & 1) * 32;
    const int wn = (wid >> 1) * 32;

    // A producer: 64 rows x 256B, each thread 64B
    const char* asrcB = (const char*)g_V
        + (size_t)(m0t + (tid >> 2)) * 4096 + (tid & 3) * 64;
    const uint32_t adst = sb + (uint32_t)(tid >> 2) * ROWB + (tid & 3) * 64;
    // B producer: 128 rows x 256B, each thread 128B
    const char* bsrcB = (const char*)g_wu
        + (size_t)(n0 + (tid >> 1)) * 256 + (tid & 1) * 128;
    const uint32_t bdst = sb + A_SM + (uint32_t)(tid >> 1) * ROWB + (tid & 1) * 128;

    // ldmatrix bases
    uint32_t aoff[2], boff[2];
#pragma unroll
    for (int mf = 0; mf < 2; ++mf)
        aoff[mf] = sb + (uint32_t)(wm + mf * 16 + (lane & 15)) * ROWB
                 + ((lane >> 4) ? 16u : 0u);
#pragma unroll
    for (int h = 0; h < 2; ++h)
        boff[h] = sb + A_SM
                + (uint32_t)(wn + h * 16 + ((lane >> 4) << 3) + (lane & 7)) * ROWB
                + (((lane >> 3) & 1) ? 16u : 0u);

    float oacc[2][4][4][4];
#pragma unroll
    for (int mf = 0; mf < 2; ++mf)
#pragma unroll
        for (int nf = 0; nf < 4; ++nf)
#pragma unroll
            for (int e = 0; e < 4; ++e)
#pragma unroll
                for (int o = 0; o < 4; ++o) oacc[mf][nf][e][o] = 0.f;

    // prefetch pos 0,1 into stage 0
    {
#pragma unroll
        for (int j = 0; j < 2; ++j) {
            const char* as = asrcB + j * 256;
            const char* bs = bsrcB + (size_t)j * (COUT * 256);
            const uint32_t so = (uint32_t)j * SUB;
#pragma unroll
            for (int c = 0; c < 4; ++c) cpa16(adst + so + c * 16, as + c * 16);
#pragma unroll
            for (int c = 0; c < 8; ++c) cpa16(bdst + so + c * 16, bs + c * 16);
        }
        cpa_commit();
    }

#pragma unroll 1
    for (int pp = 0; pp < 8; ++pp) {
        cpa_wait<0>();
        __syncthreads();
        if (pp < 7) {                   // prefetch pos 2pp+2, 2pp+3 into other stage
            const uint32_t sn = (uint32_t)((pp + 1) & 1) * STG2;
#pragma unroll
            for (int j = 0; j < 2; ++j) {
                const int pn = 2 * pp + 2 + j;
                const char* as = asrcB + pn * 256;
                const char* bs = bsrcB + (size_t)pn * (COUT * 256);
                const uint32_t so = sn + (uint32_t)j * SUB;
#pragma unroll
                for (int c = 0; c < 4; ++c) cpa16(adst + so + c * 16, as + c * 16);
#pragma unroll
                for (int c = 0; c < 8; ++c) cpa16(bdst + so + c * 16, bs + c * 16);
            }
            cpa_commit();
        }

        // ---- interleaved pos pair: 16 independent accumulator targets ----
        const uint32_t so0 = (uint32_t)(pp & 1) * STG2;
        const uint32_t so1 = so0 + SUB;
        float f0[2][4][4], f1[2][4][4];
#pragma unroll
        for (int mf = 0; mf < 2; ++mf)
#pragma unroll
            for (int nf = 0; nf < 4; ++nf)
#pragma unroll
                for (int e = 0; e < 4; ++e) { f0[mf][nf][e] = 0.f; f1[mf][nf][e] = 0.f; }

#pragma unroll
        for (int ks = 0; ks < 8; ++ks) {
            uint32_t a0[2][4], b0[2][4], a1[2][4], b1[2][4];
            ldsm4(a0[0], aoff[0] + so0 + ks * 32);
            ldsm4(a0[1], aoff[1] + so0 + ks * 32);
            ldsm4(b0[0], boff[0] + so0 + ks * 32);
            ldsm4(b0[1], boff[1] + so0 + ks * 32);
            ldsm4(a1[0], aoff[0] + so1 + ks * 32);
            ldsm4(a1[1], aoff[1] + so1 + ks * 32);
            ldsm4(b1[0], boff[0] + so1 + ks * 32);
            ldsm4(b1[1], boff[1] + so1 + ks * 32);
#pragma unroll
            for (int mf = 0; mf < 2; ++mf)
#pragma unroll
                for (int nf = 0; nf < 4; ++nf)
                    mma16816(f0[mf][nf], a0[mf], &b0[nf >> 1][(nf & 1) * 2]);
#pragma unroll
            for (int mf = 0; mf < 2; ++mf)
#pragma unroll
                for (int nf = 0; nf < 4; ++nf)
                    mma16816(f1[mf][nf], a1[mf], &b1[nf >> 1][(nf & 1) * 2]);
        }
        wg_accum(2 * pp,     f0, oacc);
        wg_accum(2 * pp + 1, f1, oacc);
    }

    __syncthreads();                    // mainloop smem reads done

    // stage 2x2 outputs: ep4[co][tile] with padded stride EPS
    float4* ep4 = (float4*)smem;        // 128*65*16 = 133120 <= SM_TOTAL
    {
        const int quad = lane >> 2, tq = lane & 3;
#pragma unroll
        for (int mf = 0; mf < 2; ++mf)
#pragma unroll
            for (int nf = 0; nf < 4; ++nf)
#pragma unroll
                for (int e = 0; e < 4; ++e) {
                    const int m_l  = wm + mf * 16 + quad + 8 * (e >> 1);
                    const int co_l = wn + nf * 8 + tq * 2 + (e & 1);
                    ep4[co_l * EPS + m_l] = make_float4(
                        oacc[mf][nf][e][0], oacc[mf][nf][e][1],
                        oacc[mf][nf][e][2], oacc[mf][nf][e][3]);
                }
    }
    __syncthreads();

    // writer: 2x2 pixels per (tile, co), + bias
    {
        const int m = tid & 63, grp = tid >> 6;   // 4 groups x 32 co
        const int tg = m0t + m;
        const int b = tg / TPI;
        const int rr = tg - b * TPI;
        const int ty = rr / 27, tx = rr - ty * 27;
        float* ob = out + (size_t)b * COUT * NPIX + (2 * ty) * WOUT + 2 * tx;
#pragma unroll
        for (int cc = 0; cc < 32; ++cc) {
            const int co_l = grp * 32 + cc;
            float4 v = ep4[co_l * EPS + m];
            const float bv = __ldg(bias + n0 + co_l);
            float* pp = ob + (size_t)(n0 + co_l) * NPIX;
            *(float2*)pp          = make_float2(v.x + bv, v.y + bv);
            *(float2*)(pp + WOUT) = make_float2(v.z + bv, v.w + bv);
        }
    }
}

// ---------------- launch ----------------
extern "C" void kernel_launch(void* const* d_in, const int* in_sizes, int n_in,
                              void* d_out, int out_size) {
    const float* x    = (const float*)d_in[0];
    const float* w    = (const float*)d_in[1];
    const float* bias = (const float*)d_in[2];
    const float* wp   = (const float*)d_in[3];
    const float* wn   = (const float*)d_in[4];
    float* out = (float*)d_out;

    maxabs_kernel<<<256, 256>>>(w, NW);
    wtrans_kernel<<<COUT, 128>>>(w, wp, wn);

    cudaFuncSetAttribute(xtrans_kernel,
                         cudaFuncAttributeMaxDynamicSharedMemorySize, XT_SM);
    xtrans_kernel<<<BATCH * 27, 256, XT_SM>>>(x);

    cudaFuncSetAttribute(wg_gemm_kernel,
                         cudaFuncAttributeMaxDynamicSharedMemorySize, SM_TOTAL);
    dim3 grid(COUT / 128, NTILES / 64);   // 2 x 729 (co fast -> A L2 reuse)
    wg_gemm_kernel<<<grid, 256, SM_TOTAL>>>(bias, out);
}

// round 14
// speedup vs baseline: 1.2231x; 1.2231x over previous
#include <cuda_runtime.h>
#include <cuda_fp16.h>
#include <cstdint>

// ------------- problem constants -------------
#define CIN   128
#define COUT  256
#define HIN   56
#define WIN   56
#define HOUT  54
#define WOUT  54
#define NPIX  (HOUT*WOUT)
#define BATCH 64
#define TPI   729                 // 27x27 winograd tiles per image
#define NTILES (BATCH*TPI)        // 46656
#define NW    (COUT*CIN*9)

// GEMM smem: 2 stages x (A 64x272B + B 128x272B); epilogue f32x4 [128][65]
#define ROWB  272
#define A_SM  (64*ROWB)           // 17408
#define B_SM  (128*ROWB)          // 34816
#define STG   (A_SM + B_SM)       // 52224
#define EPS   65
#define SM_TOTAL 133120           // max(2*STG=104448, 128*65*16=133120)

// ------------- device scratch -------------
__device__ int g_max_bits = 0;    // idempotent across replays (same inputs)
__device__ __align__(256) __half g_xh[(size_t)BATCH*HIN*WIN*CIN];  // NHWC fp16
__device__ __align__(256) __half g_V[(size_t)NTILES*16*CIN];       // [tile][pos][ci]
__device__ __align__(256) __half g_wu[16*COUT*CIN];                // [pos][co][ci]

// ------------- helpers -------------
__device__ __forceinline__ uint32_t smem_u32(const void* p) {
    uint32_t a;
    asm("{ .reg .u64 t; cvta.to.shared.u64 t, %1; cvt.u32.u64 %0, t; }"
        : "=r"(a) : "l"(p));
    return a;
}
__device__ __forceinline__ void cpa16(uint32_t dst, const void* src) {
    asm volatile("cp.async.cg.shared.global [%0], [%1], 16;"
                 :: "r"(dst), "l"(src) : "memory");
}
__device__ __forceinline__ void cpa_commit() {
    asm volatile("cp.async.commit_group;" ::: "memory");
}
template <int N>
__device__ __forceinline__ void cpa_wait() {
    asm volatile("cp.async.wait_group %0;" :: "n"(N) : "memory");
}
__device__ __forceinline__ void ldsm4(uint32_t* r, uint32_t a) {
    asm volatile("ldmatrix.sync.aligned.m8n8.x4.shared.b16 {%0,%1,%2,%3}, [%4];"
                 : "=r"(r[0]), "=r"(r[1]), "=r"(r[2]), "=r"(r[3]) : "r"(a));
}
__device__ __forceinline__ void mma16816(float* d, const uint32_t* a, const uint32_t* b) {
    asm volatile(
        "mma.sync.aligned.m16n8k16.row.col.f32.f16.f16.f32 "
        "{%0,%1,%2,%3}, {%4,%5,%6,%7}, {%8,%9}, {%0,%1,%2,%3};"
        : "+f"(d[0]), "+f"(d[1]), "+f"(d[2]), "+f"(d[3])
        : "r"(a[0]), "r"(a[1]), "r"(a[2]), "r"(a[3]), "r"(b[0]), "r"(b[1]));
}

// ---------------- kernel 1: max |w| ----------------
__global__ void maxabs_kernel(const float* __restrict__ w, int n) {
    float m = 0.f;
    for (int i = blockIdx.x * blockDim.x + threadIdx.x; i < n; i += gridDim.x * blockDim.x)
        m = fmaxf(m, fabsf(w[i]));
#pragma unroll
    for (int o = 16; o; o >>= 1) m = fmaxf(m, __shfl_xor_sync(0xffffffffu, m, o));
    __shared__ float sm[8];
    int lane = threadIdx.x & 31, wid = threadIdx.x >> 5;
    if (lane == 0) sm[wid] = m;
    __syncthreads();
    if (wid == 0) {
        m = (lane < 8) ? sm[lane] : 0.f;
#pragma unroll
        for (int o = 4; o; o >>= 1) m = fmaxf(m, __shfl_xor_sync(0xffffffffu, m, o));
        if (lane == 0) atomicMax(&g_max_bits, __float_as_int(m));
    }
}

// ---------------- kernel 2: quantize + winograd weight transform ----------------
__global__ void __launch_bounds__(128)
wtrans_kernel(const float* __restrict__ w,
              const float* __restrict__ wp,
              const float* __restrict__ wn) {
    __shared__ __align__(16) __half stg[16][128];
    const int co = blockIdx.x, ci = threadIdx.x;
    const float t   = 0.05f * __int_as_float(g_max_bits);
    const float wpa = fabsf(wp[0]);
    const float wna = fabsf(wn[0]);
    const float* g = w + ((size_t)co * CIN + ci) * 9;
    float q[9];
#pragma unroll
    for (int k = 0; k < 9; ++k) {
        float v = g[k];
        q[k] = (v > t) ? wpa : ((v < -t) ? -wna : 0.f);
    }
    float T[4][3];
#pragma unroll
    for (int c = 0; c < 3; ++c) {
        T[0][c] = q[c];
        T[1][c] = 0.5f * (q[c] + q[3 + c] + q[6 + c]);
        T[2][c] = 0.5f * (q[c] - q[3 + c] + q[6 + c]);
        T[3][c] = q[6 + c];
    }
#pragma unroll
    for (int r = 0; r < 4; ++r) {
        float u0 = T[r][0];
        float u1 = 0.5f * (T[r][0] + T[r][1] + T[r][2]);
        float u2 = 0.5f * (T[r][0] - T[r][1] + T[r][2]);
        float u3 = T[r][2];
        stg[r * 4 + 0][ci] = __float2half_rn(u0);
        stg[r * 4 + 1][ci] = __float2half_rn(u1);
        stg[r * 4 + 2][ci] = __float2half_rn(u2);
        stg[r * 4 + 3][ci] = __float2half_rn(u3);
    }
    __syncthreads();
#pragma unroll
    for (int k = 0; k < 2; ++k) {
        int chunk = k * 128 + threadIdx.x;
        int pos = chunk >> 4, off = chunk & 15;
        ((uint4*)(g_wu + ((size_t)(pos * COUT + co)) * CIN))[off] =
            ((const uint4*)&stg[pos][0])[off];
    }
}

// ---------------- kernel 3: x NCHW f32 -> NHWC f16 ----------------
__global__ void __launch_bounds__(256)
transpose_kernel(const float* __restrict__ x) {
    __shared__ __half tile[WIN * 130];
    int b = blockIdx.x / HIN, y = blockIdx.x % HIN;
    const float* src = x + ((size_t)b * CIN) * (HIN * WIN) + y * WIN;
    for (int i = threadIdx.x; i < CIN * WIN; i += 256) {
        int ci = i / WIN, xx = i - ci * WIN;
        tile[xx * 130 + ci] = __float2half_rn(src[(size_t)ci * (HIN * WIN) + xx]);
    }
    __syncthreads();
    __half* dst = g_xh + ((size_t)(b * HIN + y) * WIN) * CIN;
    for (int i = threadIdx.x; i < CIN * WIN; i += 256) {
        int xx = i >> 7, ci = i & 127;
        dst[i] = tile[xx * 130 + ci];
    }
}

// ---------------- kernel 4: input transform V = B^T d B ----------------
__global__ void __launch_bounds__(256)
itrans_kernel() {
    __shared__ __align__(16) __half stg[2][16][128];
    const int tl = threadIdx.x >> 7, ci = threadIdx.x & 127;
    const int tile = blockIdx.x * 2 + tl;
    const int b = tile / TPI;
    const int r = tile - b * TPI;
    const int ty = r / 27, tx = r - ty * 27;
    const __half* src = g_xh + ((size_t)((b * HIN + 2 * ty) * WIN + 2 * tx)) * CIN + ci;
    float d[4][4];
#pragma unroll
    for (int yy = 0; yy < 4; ++yy)
#pragma unroll
        for (int xx = 0; xx < 4; ++xx)
            d[yy][xx] = __half2float(src[(size_t)(yy * WIN + xx) * CIN]);
    float tm[4][4];
#pragma unroll
    for (int c = 0; c < 4; ++c) {
        tm[0][c] = d[0][c] - d[2][c];
        tm[1][c] = d[1][c] + d[2][c];
        tm[2][c] = d[2][c] - d[1][c];
        tm[3][c] = d[1][c] - d[3][c];
    }
#pragma unroll
    for (int rr = 0; rr < 4; ++rr) {
        float v0 = tm[rr][0] - tm[rr][2];
        float v1 = tm[rr][1] + tm[rr][2];
        float v2 = tm[rr][2] - tm[rr][1];
        float v3 = tm[rr][1] - tm[rr][3];
        stg[tl][rr * 4 + 0][ci] = __float2half_rn(v0);
        stg[tl][rr * 4 + 1][ci] = __float2half_rn(v1);
        stg[tl][rr * 4 + 2][ci] = __float2half_rn(v2);
        stg[tl][rr * 4 + 3][ci] = __float2half_rn(v3);
    }
    __syncthreads();
    uint4* d4 = (uint4*)(g_V + (size_t)blockIdx.x * 2 * 16 * CIN);
    const uint4* s4 = (const uint4*)&stg[0][0][0];
    d4[threadIdx.x]       = s4[threadIdx.x];
    d4[threadIdx.x + 256] = s4[threadIdx.x + 256];
}

// ---------------- kernel 5: winograd GEMM, fully unrolled pos loop ----------------
__global__ void __launch_bounds__(512, 1)
wg_gemm_kernel(const float* __restrict__ bias, float* __restrict__ out) {
    extern __shared__ char smem[];
    const uint32_t sb = smem_u32(smem);
    const int tid = threadIdx.x;
    const int wid = tid >> 5, lane = tid & 31;
    const int n0  = blockIdx.x * 128;      // cout base (fast axis -> A L2 reuse)
    const int m0t = blockIdx.y * 64;       // tile base

    // warp grid 2(m) x 8(n); warp tile 32(m) x 16(n)
    const int wm = (wid & 1) * 32;
    const int wn = (wid >> 1) * 16;

    // A producer: 64 rows x 256B, each thread 32B
    const char* asrcB = (const char*)g_V
        + (size_t)(m0t + (tid >> 3)) * 4096 + (tid & 7) * 32;
    const uint32_t adst = sb + (uint32_t)(tid >> 3) * ROWB + (tid & 7) * 32;
    // B producer: 128 rows x 256B, each thread 64B
    const char* bsrcB = (const char*)g_wu
        + (size_t)(n0 + (tid >> 2)) * 256 + (tid & 3) * 64;
    const uint32_t bdst = sb + A_SM + (uint32_t)(tid >> 2) * ROWB + (tid & 3) * 64;

    // ldmatrix bases
    uint32_t aoff[2];
#pragma unroll
    for (int mf = 0; mf < 2; ++mf)
        aoff[mf] = sb + (uint32_t)(wm + mf * 16 + (lane & 15)) * ROWB
                 + ((lane >> 4) ? 16u : 0u);
    const uint32_t boff = sb + A_SM
        + (uint32_t)(wn + ((lane >> 4) << 3) + (lane & 7)) * ROWB
        + (((lane >> 3) & 1) ? 16u : 0u);

    // persistent winograd-output accumulators
    float oacc[2][2][4][4];
#pragma unroll
    for (int mf = 0; mf < 2; ++mf)
#pragma unroll
        for (int nf = 0; nf < 2; ++nf)
#pragma unroll
            for (int e = 0; e < 4; ++e)
#pragma unroll
                for (int o = 0; o < 4; ++o) oacc[mf][nf][e][o] = 0.f;

    // prefetch pos 0 into stage 0
    {
#pragma unroll
        for (int c = 0; c < 2; ++c) cpa16(adst + c * 16, asrcB + c * 16);
#pragma unroll
        for (int c = 0; c < 4; ++c) cpa16(bdst + c * 16, bsrcB + c * 16);
        cpa_commit();
    }

#pragma unroll
    for (int pos = 0; pos < 16; ++pos) {
        __syncthreads();              // readers of stage (pos+1)&1 done
        if (pos + 1 < 16) {
            const char* as = asrcB + (pos + 1) * 256;
            const char* bs = bsrcB + (size_t)(pos + 1) * (COUT * 256);
            const uint32_t so = (uint32_t)((pos + 1) & 1) * STG;
#pragma unroll
            for (int c = 0; c < 2; ++c) cpa16(adst + so + c * 16, as + c * 16);
#pragma unroll
            for (int c = 0; c < 4; ++c) cpa16(bdst + so + c * 16, bs + c * 16);
        }
        cpa_commit();
        cpa_wait<1>();
        __syncthreads();

        const uint32_t soff = (uint32_t)(pos & 1) * STG;

        float facc[2][2][4];
#pragma unroll
        for (int mf = 0; mf < 2; ++mf)
#pragma unroll
            for (int nf = 0; nf < 2; ++nf)
#pragma unroll
                for (int e = 0; e < 4; ++e) facc[mf][nf][e] = 0.f;

#pragma unroll
        for (int ks = 0; ks < 8; ++ks) {
            uint32_t afr[2][4], bfr[4];
            ldsm4(afr[0], aoff[0] + soff + ks * 32);
            ldsm4(afr[1], aoff[1] + soff + ks * 32);
            ldsm4(bfr, boff + soff + ks * 32);
            mma16816(facc[0][0], afr[0], bfr);
            mma16816(facc[0][1], afr[0], bfr + 2);
            mma16816(facc[1][0], afr[1], bfr);
            mma16816(facc[1][1], afr[1], bfr + 2);
        }

        // compile-time output-transform coefficients: w in {0, +1, -1}
        const int p = pos >> 2, q = pos & 3;
        const float cp0 = (p == 3) ? 0.f : 1.f;
        const float cp1 = (p == 0) ? 0.f : ((p == 1) ? 1.f : -1.f);
        const float cq0 = (q == 3) ? 0.f : 1.f;
        const float cq1 = (q == 0) ? 0.f : ((q == 1) ? 1.f : -1.f);
        const float w00 = cp0 * cq0, w01 = cp0 * cq1;
        const float w10 = cp1 * cq0, w11 = cp1 * cq1;
#pragma unroll
        for (int mf = 0; mf < 2; ++mf)
#pragma unroll
            for (int nf = 0; nf < 2; ++nf)
#pragma unroll
                for (int e = 0; e < 4; ++e) {
                    const float f = facc[mf][nf][e];
                    if (w00 != 0.f) oacc[mf][nf][e][0] += w00 * f;
                    if (w01 != 0.f) oacc[mf][nf][e][1] += w01 * f;
                    if (w10 != 0.f) oacc[mf][nf][e][2] += w10 * f;
                    if (w11 != 0.f) oacc[mf][nf][e][3] += w11 * f;
                }
    }
    __syncthreads();                  // mainloop smem reads done

    // stage 2x2 outputs: ep4[co][tile] with padded stride EPS
    float4* ep4 = (float4*)smem;      // 128*65*16 = 133120
    {
        const int quad = lane >> 2, tq = lane & 3;
#pragma unroll
        for (int mf = 0; mf < 2; ++mf)
#pragma unroll
            for (int nf = 0; nf < 2; ++nf)
#pragma unroll
                for (int e = 0; e < 4; ++e) {
                    const int m_l  = wm + mf * 16 + quad + 8 * (e >> 1);
                    const int co_l = wn + nf * 8 + tq * 2 + (e & 1);
                    ep4[co_l * EPS + m_l] = make_float4(
                        oacc[mf][nf][e][0], oacc[mf][nf][e][1],
                        oacc[mf][nf][e][2], oacc[mf][nf][e][3]);
                }
    }
    __syncthreads();

    // writer: 2x2 pixels per (tile, co), + bias
    {
        const int m = tid & 63, grp = tid >> 6;   // 8 groups x 16 co
        const int tg = m0t + m;
        const int b = tg / TPI;
        const int rr = tg - b * TPI;
        const int ty = rr / 27, tx = rr - ty * 27;
        float* ob = out + (size_t)b * COUT * NPIX + (2 * ty) * WOUT + 2 * tx;
#pragma unroll
        for (int cc = 0; cc < 16; ++cc) {
            const int co_l = grp * 16 + cc;
            float4 v = ep4[co_l * EPS + m];
            const float bv = __ldg(bias + n0 + co_l);
            float* pp = ob + (size_t)(n0 + co_l) * NPIX;
            *(float2*)pp          = make_float2(v.x + bv, v.y + bv);
            *(float2*)(pp + WOUT) = make_float2(v.z + bv, v.w + bv);
        }
    }
}

// ---------------- launch ----------------
extern "C" void kernel_launch(void* const* d_in, const int* in_sizes, int n_in,
                              void* d_out, int out_size) {
    const float* x    = (const float*)d_in[0];
    const float* w    = (const float*)d_in[1];
    const float* bias = (const float*)d_in[2];
    const float* wp   = (const float*)d_in[3];
    const float* wn   = (const float*)d_in[4];
    float* out = (float*)d_out;

    maxabs_kernel<<<256, 256>>>(w, NW);
    wtrans_kernel<<<COUT, 128>>>(w, wp, wn);
    transpose_kernel<<<BATCH * HIN, 256>>>(x);
    itrans_kernel<<<NTILES / 2, 256>>>();

    cudaFuncSetAttribute(wg_gemm_kernel,
                         cudaFuncAttributeMaxDynamicSharedMemorySize, SM_TOTAL);
    dim3 grid(COUT / 128, NTILES / 64);   // 2 x 729 (co fast -> A L2 reuse)
    wg_gemm_kernel<<<grid, 512, SM_TOTAL>>>(bias, out);
}

// round 15
// speedup vs baseline: 1.4098x; 1.1527x over previous
#include <cuda_runtime.h>
#include <cuda_fp16.h>
#include <cstdint>

// ------------- problem constants -------------
#define CIN   128
#define COUT  256
#define HIN   56
#define WIN   56
#define HOUT  54
#define WOUT  54
#define NPIX  (HOUT*WOUT)
#define BATCH 64
#define TPI   729                 // 27x27 winograd tiles per image
#define NTILES (BATCH*TPI)        // 46656
#define NW    (COUT*CIN*9)

// GEMM smem: 2 stages x (A 64x256B + B 128x256B), XOR-swizzled rows
#define ROWB  256
#define A_SM  (64*ROWB)           // 16384
#define B_SM  (128*ROWB)          // 32768
#define STG   (A_SM + B_SM)       // 49152
#define EPS   65
#define SM_TOTAL 133120           // epilogue f32x4 [128][65] dominates

// ------------- device scratch -------------
__device__ int g_max_bits = 0;    // idempotent across replays (same inputs)
__device__ __align__(256) __half g_xh[(size_t)BATCH*HIN*WIN*CIN];  // NHWC fp16
__device__ __align__(256) __half g_V[(size_t)NTILES*16*CIN];       // [tile][pos][ci]
__device__ __align__(256) __half g_wu[16*COUT*CIN];                // [pos][co][ci]

// ------------- helpers -------------
__device__ __forceinline__ uint32_t smem_u32(const void* p) {
    uint32_t a;
    asm("{ .reg .u64 t; cvta.to.shared.u64 t, %1; cvt.u32.u64 %0, t; }"
        : "=r"(a) : "l"(p));
    return a;
}
__device__ __forceinline__ void cpa16(uint32_t dst, const void* src) {
    asm volatile("cp.async.cg.shared.global [%0], [%1], 16;"
                 :: "r"(dst), "l"(src) : "memory");
}
__device__ __forceinline__ void cpa_commit() {
    asm volatile("cp.async.commit_group;" ::: "memory");
}
template <int N>
__device__ __forceinline__ void cpa_wait() {
    asm volatile("cp.async.wait_group %0;" :: "n"(N) : "memory");
}
__device__ __forceinline__ void ldsm4(uint32_t* r, uint32_t a) {
    asm volatile("ldmatrix.sync.aligned.m8n8.x4.shared.b16 {%0,%1,%2,%3}, [%4];"
                 : "=r"(r[0]), "=r"(r[1]), "=r"(r[2]), "=r"(r[3]) : "r"(a));
}
__device__ __forceinline__ void mma16816(float* d, const uint32_t* a, const uint32_t* b) {
    asm volatile(
        "mma.sync.aligned.m16n8k16.row.col.f32.f16.f16.f32 "
        "{%0,%1,%2,%3}, {%4,%5,%6,%7}, {%8,%9}, {%0,%1,%2,%3};"
        : "+f"(d[0]), "+f"(d[1]), "+f"(d[2]), "+f"(d[3])
        : "r"(a[0]), "r"(a[1]), "r"(a[2]), "r"(a[3]), "r"(b[0]), "r"(b[1]));
}

// ---------------- kernel 1: max |w| ----------------
__global__ void maxabs_kernel(const float* __restrict__ w, int n) {
    float m = 0.f;
    for (int i = blockIdx.x * blockDim.x + threadIdx.x; i < n; i += gridDim.x * blockDim.x)
        m = fmaxf(m, fabsf(w[i]));
#pragma unroll
    for (int o = 16; o; o >>= 1) m = fmaxf(m, __shfl_xor_sync(0xffffffffu, m, o));
    __shared__ float sm[8];
    int lane = threadIdx.x & 31, wid = threadIdx.x >> 5;
    if (lane == 0) sm[wid] = m;
    __syncthreads();
    if (wid == 0) {
        m = (lane < 8) ? sm[lane] : 0.f;
#pragma unroll
        for (int o = 4; o; o >>= 1) m = fmaxf(m, __shfl_xor_sync(0xffffffffu, m, o));
        if (lane == 0) atomicMax(&g_max_bits, __float_as_int(m));
    }
}

// ---------------- kernel 2: quantize + winograd weight transform ----------------
__global__ void __launch_bounds__(128)
wtrans_kernel(const float* __restrict__ w,
              const float* __restrict__ wp,
              const float* __restrict__ wn) {
    __shared__ __align__(16) __half stg[16][128];
    const int co = blockIdx.x, ci = threadIdx.x;
    const float t   = 0.05f * __int_as_float(g_max_bits);
    const float wpa = fabsf(wp[0]);
    const float wna = fabsf(wn[0]);
    const float* g = w + ((size_t)co * CIN + ci) * 9;
    float q[9];
#pragma unroll
    for (int k = 0; k < 9; ++k) {
        float v = g[k];
        q[k] = (v > t) ? wpa : ((v < -t) ? -wna : 0.f);
    }
    float T[4][3];
#pragma unroll
    for (int c = 0; c < 3; ++c) {
        T[0][c] = q[c];
        T[1][c] = 0.5f * (q[c] + q[3 + c] + q[6 + c]);
        T[2][c] = 0.5f * (q[c] - q[3 + c] + q[6 + c]);
        T[3][c] = q[6 + c];
    }
#pragma unroll
    for (int r = 0; r < 4; ++r) {
        float u0 = T[r][0];
        float u1 = 0.5f * (T[r][0] + T[r][1] + T[r][2]);
        float u2 = 0.5f * (T[r][0] - T[r][1] + T[r][2]);
        float u3 = T[r][2];
        stg[r * 4 + 0][ci] = __float2half_rn(u0);
        stg[r * 4 + 1][ci] = __float2half_rn(u1);
        stg[r * 4 + 2][ci] = __float2half_rn(u2);
        stg[r * 4 + 3][ci] = __float2half_rn(u3);
    }
    __syncthreads();
#pragma unroll
    for (int k = 0; k < 2; ++k) {
        int chunk = k * 128 + threadIdx.x;
        int pos = chunk >> 4, off = chunk & 15;
        ((uint4*)(g_wu + ((size_t)(pos * COUT + co)) * CIN))[off] =
            ((const uint4*)&stg[pos][0])[off];
    }
}

// ---------------- kernel 3: x NCHW f32 -> NHWC f16 ----------------
__global__ void __launch_bounds__(256)
transpose_kernel(const float* __restrict__ x) {
    __shared__ __half tile[WIN * 130];
    int b = blockIdx.x / HIN, y = blockIdx.x % HIN;
    const float* src = x + ((size_t)b * CIN) * (HIN * WIN) + y * WIN;
    for (int i = threadIdx.x; i < CIN * WIN; i += 256) {
        int ci = i / WIN, xx = i - ci * WIN;
        tile[xx * 130 + ci] = __float2half_rn(src[(size_t)ci * (HIN * WIN) + xx]);
    }
    __syncthreads();
    __half* dst = g_xh + ((size_t)(b * HIN + y) * WIN) * CIN;
    for (int i = threadIdx.x; i < CIN * WIN; i += 256) {
        int xx = i >> 7, ci = i & 127;
        dst[i] = tile[xx * 130 + ci];
    }
}

// ---------------- kernel 4: input transform V = B^T d B ----------------
__global__ void __launch_bounds__(256)
itrans_kernel() {
    __shared__ __align__(16) __half stg[2][16][128];
    const int tl = threadIdx.x >> 7, ci = threadIdx.x & 127;
    const int tile = blockIdx.x * 2 + tl;
    const int b = tile / TPI;
    const int r = tile - b * TPI;
    const int ty = r / 27, tx = r - ty * 27;
    const __half* src = g_xh + ((size_t)((b * HIN + 2 * ty) * WIN + 2 * tx)) * CIN + ci;
    float d[4][4];
#pragma unroll
    for (int yy = 0; yy < 4; ++yy)
#pragma unroll
        for (int xx = 0; xx < 4; ++xx)
            d[yy][xx] = __half2float(src[(size_t)(yy * WIN + xx) * CIN]);
    float tm[4][4];
#pragma unroll
    for (int c = 0; c < 4; ++c) {
        tm[0][c] = d[0][c] - d[2][c];
        tm[1][c] = d[1][c] + d[2][c];
        tm[2][c] = d[2][c] - d[1][c];
        tm[3][c] = d[1][c] - d[3][c];
    }
#pragma unroll
    for (int rr = 0; rr < 4; ++rr) {
        float v0 = tm[rr][0] - tm[rr][2];
        float v1 = tm[rr][1] + tm[rr][2];
        float v2 = tm[rr][2] - tm[rr][1];
        float v3 = tm[rr][1] - tm[rr][3];
        stg[tl][rr * 4 + 0][ci] = __float2half_rn(v0);
        stg[tl][rr * 4 + 1][ci] = __float2half_rn(v1);
        stg[tl][rr * 4 + 2][ci] = __float2half_rn(v2);
        stg[tl][rr * 4 + 3][ci] = __float2half_rn(v3);
    }
    __syncthreads();
    uint4* d4 = (uint4*)(g_V + (size_t)blockIdx.x * 2 * 16 * CIN);
    const uint4* s4 = (const uint4*)&stg[0][0][0];
    d4[threadIdx.x]       = s4[threadIdx.x];
    d4[threadIdx.x + 256] = s4[threadIdx.x + 256];
}

// ---------------- kernel 5: winograd GEMM, swizzled smem ----------------
__global__ void __launch_bounds__(512, 1)
wg_gemm_kernel(const float* __restrict__ bias, float* __restrict__ out) {
    extern __shared__ char smem[];
    const uint32_t sb = smem_u32(smem);
    const int tid = threadIdx.x;
    const int wid = tid >> 5, lane = tid & 31;
    const int n0  = blockIdx.x * 128;      // cout base (fast axis -> A L2 reuse)
    const int m0t = blockIdx.y * 64;       // tile base

    // warp grid 2(m) x 8(n); warp tile 32(m) x 16(n)
    const int wm = (wid & 1) * 32;
    const int wn = (wid >> 1) * 16;

    // ---- A producer: thread = (row 0..63, 32B part 0..7), swizzled dst ----
    const int ar = tid >> 3, ap = tid & 7;
    const char* asrcB = (const char*)g_V + (size_t)(m0t + ar) * 4096 + ap * 32;
    const uint32_t arow = sb + (uint32_t)ar * ROWB;
    const uint32_t ac0 = (uint32_t)(((2 * ap)     ^ (ar & 7)) << 4);
    const uint32_t ac1 = (uint32_t)(((2 * ap + 1) ^ (ar & 7)) << 4);

    // ---- B producer: thread = (row 0..127, 64B part 0..3), swizzled dst ----
    const int br = tid >> 2, bp = tid & 3;
    const char* bsrcB = (const char*)g_wu + (size_t)(n0 + br) * 256 + bp * 64;
    const uint32_t brow = sb + A_SM + (uint32_t)br * ROWB;
    uint32_t bc[4];
#pragma unroll
    for (int j = 0; j < 4; ++j)
        bc[j] = (uint32_t)(((4 * bp + j) ^ (br & 7)) << 4);

    // ---- ldmatrix bases (swizzle applied per ks) ----
    uint32_t abase[2], as7[2];
#pragma unroll
    for (int mf = 0; mf < 2; ++mf) {
        const int r = wm + mf * 16 + (lane & 15);
        abase[mf] = sb + (uint32_t)r * ROWB;
        as7[mf]   = (uint32_t)(r & 7);
    }
    const uint32_t ahi = (uint32_t)(lane >> 4);
    const int rb = wn + ((lane >> 4) << 3) + (lane & 7);
    const uint32_t bbase = sb + A_SM + (uint32_t)rb * ROWB;
    const uint32_t bs7   = (uint32_t)(rb & 7);
    const uint32_t bhi   = (uint32_t)((lane >> 3) & 1);

    // persistent winograd-output accumulators
    float oacc[2][2][4][4];
#pragma unroll
    for (int mf = 0; mf < 2; ++mf)
#pragma unroll
        for (int nf = 0; nf < 2; ++nf)
#pragma unroll
            for (int e = 0; e < 4; ++e)
#pragma unroll
                for (int o = 0; o < 4; ++o) oacc[mf][nf][e][o] = 0.f;

    // prefetch pos 0 into stage 0
    {
        cpa16(arow + ac0, asrcB);
        cpa16(arow + ac1, asrcB + 16);
#pragma unroll
        for (int j = 0; j < 4; ++j) cpa16(brow + bc[j], bsrcB + j * 16);
        cpa_commit();
    }

#pragma unroll
    for (int pos = 0; pos < 16; ++pos) {
        __syncthreads();              // readers of stage (pos+1)&1 done
        if (pos + 1 < 16) {
            const char* as = asrcB + (pos + 1) * 256;
            const char* bs = bsrcB + (size_t)(pos + 1) * (COUT * 256);
            const uint32_t so = (uint32_t)((pos + 1) & 1) * STG;
            cpa16(arow + so + ac0, as);
            cpa16(arow + so + ac1, as + 16);
#pragma unroll
            for (int j = 0; j < 4; ++j) cpa16(brow + so + bc[j], bs + j * 16);
        }
        cpa_commit();
        cpa_wait<1>();
        __syncthreads();

        const uint32_t soff = (uint32_t)(pos & 1) * STG;

        float facc[2][2][4];
#pragma unroll
        for (int mf = 0; mf < 2; ++mf)
#pragma unroll
            for (int nf = 0; nf < 2; ++nf)
#pragma unroll
                for (int e = 0; e < 4; ++e) facc[mf][nf][e] = 0.f;

#pragma unroll
        for (int ks = 0; ks < 8; ++ks) {
            uint32_t afr[2][4], bfr[4];
            const uint32_t kc = (uint32_t)(ks << 1);
            ldsm4(afr[0], abase[0] + soff + (((kc | ahi) ^ as7[0]) << 4));
            ldsm4(afr[1], abase[1] + soff + (((kc | ahi) ^ as7[1]) << 4));
            ldsm4(bfr,    bbase    + soff + (((kc | bhi) ^ bs7)    << 4));
            mma16816(facc[0][0], afr[0], bfr);
            mma16816(facc[0][1], afr[0], bfr + 2);
            mma16816(facc[1][0], afr[1], bfr);
            mma16816(facc[1][1], afr[1], bfr + 2);
        }

        // compile-time output-transform coefficients: w in {0, +1, -1}
        const int p = pos >> 2, q = pos & 3;
        const float cp0 = (p == 3) ? 0.f : 1.f;
        const float cp1 = (p == 0) ? 0.f : ((p == 1) ? 1.f : -1.f);
        const float cq0 = (q == 3) ? 0.f : 1.f;
        const float cq1 = (q == 0) ? 0.f : ((q == 1) ? 1.f : -1.f);
        const float w00 = cp0 * cq0, w01 = cp0 * cq1;
        const float w10 = cp1 * cq0, w11 = cp1 * cq1;
#pragma unroll
        for (int mf = 0; mf < 2; ++mf)
#pragma unroll
            for (int nf = 0; nf < 2; ++nf)
#pragma unroll
                for (int e = 0; e < 4; ++e) {
                    const float f = facc[mf][nf][e];
                    if (w00 != 0.f) oacc[mf][nf][e][0] += w00 * f;
                    if (w01 != 0.f) oacc[mf][nf][e][1] += w01 * f;
                    if (w10 != 0.f) oacc[mf][nf][e][2] += w10 * f;
                    if (w11 != 0.f) oacc[mf][nf][e][3] += w11 * f;
                }
    }
    __syncthreads();                  // mainloop smem reads done

    // stage 2x2 outputs: ep4[co][tile] with padded stride EPS
    float4* ep4 = (float4*)smem;      // 128*65*16 = 133120
    {
        const int quad = lane >> 2, tq = lane & 3;
#pragma unroll
        for (int mf = 0; mf < 2; ++mf)
#pragma unroll
            for (int nf = 0; nf < 2; ++nf)
#pragma unroll
                for (int e = 0; e < 4; ++e) {
                    const int m_l  = wm + mf * 16 + quad + 8 * (e >> 1);
                    const int co_l = wn + nf * 8 + tq * 2 + (e & 1);
                    ep4[co_l * EPS + m_l] = make_float4(
                        oacc[mf][nf][e][0], oacc[mf][nf][e][1],
                        oacc[mf][nf][e][2], oacc[mf][nf][e][3]);
                }
    }
    __syncthreads();

    // writer: 2x2 pixels per (tile, co), + bias
    {
        const int m = tid & 63, grp = tid >> 6;   // 8 groups x 16 co
        const int tg = m0t + m;
        const int b = tg / TPI;
        const int rr = tg - b * TPI;
        const int ty = rr / 27, tx = rr - ty * 27;
        float* ob = out + (size_t)b * COUT * NPIX + (2 * ty) * WOUT + 2 * tx;
#pragma unroll
        for (int cc = 0; cc < 16; ++cc) {
            const int co_l = grp * 16 + cc;
            float4 v = ep4[co_l * EPS + m];
            const float bv = __ldg(bias + n0 + co_l);
            float* pp = ob + (size_t)(n0 + co_l) * NPIX;
            *(float2*)pp          = make_float2(v.x + bv, v.y + bv);
            *(float2*)(pp + WOUT) = make_float2(v.z + bv, v.w + bv);
        }
    }
}

// ---------------- launch ----------------
extern "C" void kernel_launch(void* const* d_in, const int* in_sizes, int n_in,
                              void* d_out, int out_size) {
    const float* x    = (const float*)d_in[0];
    const float* w    = (const float*)d_in[1];
    const float* bias = (const float*)d_in[2];
    const float* wp   = (const float*)d_in[3];
    const float* wn   = (const float*)d_in[4];
    float* out = (float*)d_out;

    maxabs_kernel<<<256, 256>>>(w, NW);
    wtrans_kernel<<<COUT, 128>>>(w, wp, wn);
    transpose_kernel<<<BATCH * HIN, 256>>>(x);
    itrans_kernel<<<NTILES / 2, 256>>>();

    cudaFuncSetAttribute(wg_gemm_kernel,
                         cudaFuncAttributeMaxDynamicSharedMemorySize, SM_TOTAL);
    dim3 grid(COUT / 128, NTILES / 64);   // 2 x 729 (co fast -> A L2 reuse)
    wg_gemm_kernel<<<grid, 512, SM_TOTAL>>>(bias, out);
}

// round 16
// speedup vs baseline: 1.5217x; 1.0793x over previous
#include <cuda_runtime.h>
#include <cuda_fp16.h>
#include <cstdint>

// ------------- problem constants -------------
#define CIN   128
#define COUT  256
#define HIN   56
#define WIN   56
#define HOUT  54
#define WOUT  54
#define NPIX  (HOUT*WOUT)
#define BATCH 64
#define TPI   729                 // 27x27 winograd tiles per image
#define NTILES (BATCH*TPI)        // 46656
#define NW    (COUT*CIN*9)

// GEMM smem: 2 stages x (A 64x256B + B 128x256B), XOR-swizzled rows
#define ROWB  256
#define A_SM  (64*ROWB)           // 16384
#define B_SM  (128*ROWB)          // 32768
#define STG   (A_SM + B_SM)       // 49152
#define EPS   65
#define SM_TOTAL 133120           // epilogue f32x4 [128][65] dominates

// ------------- device scratch -------------
__device__ int g_max_bits = 0;    // idempotent across replays (same inputs)
__device__ __align__(256) __half g_xh[(size_t)BATCH*HIN*WIN*CIN];  // NHWC fp16
__device__ __align__(256) __half g_V[(size_t)NTILES*16*CIN];       // [tile][pos][ci]
__device__ __align__(256) __half g_wu[16*COUT*CIN];                // [pos][co][ci]

// ------------- helpers -------------
__device__ __forceinline__ uint32_t smem_u32(const void* p) {
    uint32_t a;
    asm("{ .reg .u64 t; cvta.to.shared.u64 t, %1; cvt.u32.u64 %0, t; }"
        : "=r"(a) : "l"(p));
    return a;
}
__device__ __forceinline__ void cpa16(uint32_t dst, const void* src) {
    asm volatile("cp.async.cg.shared.global [%0], [%1], 16;"
                 :: "r"(dst), "l"(src) : "memory");
}
__device__ __forceinline__ void cpa_commit() {
    asm volatile("cp.async.commit_group;" ::: "memory");
}
template <int N>
__device__ __forceinline__ void cpa_wait() {
    asm volatile("cp.async.wait_group %0;" :: "n"(N) : "memory");
}
__device__ __forceinline__ void ldsm4(uint32_t* r, uint32_t a) {
    asm volatile("ldmatrix.sync.aligned.m8n8.x4.shared.b16 {%0,%1,%2,%3}, [%4];"
                 : "=r"(r[0]), "=r"(r[1]), "=r"(r[2]), "=r"(r[3]) : "r"(a));
}
__device__ __forceinline__ void mma16816(float* d, const uint32_t* a, const uint32_t* b) {
    asm volatile(
        "mma.sync.aligned.m16n8k16.row.col.f32.f16.f16.f32 "
        "{%0,%1,%2,%3}, {%4,%5,%6,%7}, {%8,%9}, {%0,%1,%2,%3};"
        : "+f"(d[0]), "+f"(d[1]), "+f"(d[2]), "+f"(d[3])
        : "r"(a[0]), "r"(a[1]), "r"(a[2]), "r"(a[3]), "r"(b[0]), "r"(b[1]));
}

// ---------------- kernel 1: max |w| ----------------
__global__ void maxabs_kernel(const float* __restrict__ w, int n) {
    float m = 0.f;
    for (int i = blockIdx.x * blockDim.x + threadIdx.x; i < n; i += gridDim.x * blockDim.x)
        m = fmaxf(m, fabsf(w[i]));
#pragma unroll
    for (int o = 16; o; o >>= 1) m = fmaxf(m, __shfl_xor_sync(0xffffffffu, m, o));
    __shared__ float sm[8];
    int lane = threadIdx.x & 31, wid = threadIdx.x >> 5;
    if (lane == 0) sm[wid] = m;
    __syncthreads();
    if (wid == 0) {
        m = (lane < 8) ? sm[lane] : 0.f;
#pragma unroll
        for (int o = 4; o; o >>= 1) m = fmaxf(m, __shfl_xor_sync(0xffffffffu, m, o));
        if (lane == 0) atomicMax(&g_max_bits, __float_as_int(m));
    }
}

// ---------------- kernel 2: quantize + winograd weight transform ----------------
__global__ void __launch_bounds__(128)
wtrans_kernel(const float* __restrict__ w,
              const float* __restrict__ wp,
              const float* __restrict__ wn) {
    __shared__ __align__(16) __half stg[16][128];
    const int co = blockIdx.x, ci = threadIdx.x;
    const float t   = 0.05f * __int_as_float(g_max_bits);
    const float wpa = fabsf(wp[0]);
    const float wna = fabsf(wn[0]);
    const float* g = w + ((size_t)co * CIN + ci) * 9;
    float q[9];
#pragma unroll
    for (int k = 0; k < 9; ++k) {
        float v = g[k];
        q[k] = (v > t) ? wpa : ((v < -t) ? -wna : 0.f);
    }
    float T[4][3];
#pragma unroll
    for (int c = 0; c < 3; ++c) {
        T[0][c] = q[c];
        T[1][c] = 0.5f * (q[c] + q[3 + c] + q[6 + c]);
        T[2][c] = 0.5f * (q[c] - q[3 + c] + q[6 + c]);
        T[3][c] = q[6 + c];
    }
#pragma unroll
    for (int r = 0; r < 4; ++r) {
        float u0 = T[r][0];
        float u1 = 0.5f * (T[r][0] + T[r][1] + T[r][2]);
        float u2 = 0.5f * (T[r][0] - T[r][1] + T[r][2]);
        float u3 = T[r][2];
        stg[r * 4 + 0][ci] = __float2half_rn(u0);
        stg[r * 4 + 1][ci] = __float2half_rn(u1);
        stg[r * 4 + 2][ci] = __float2half_rn(u2);
        stg[r * 4 + 3][ci] = __float2half_rn(u3);
    }
    __syncthreads();
#pragma unroll
    for (int k = 0; k < 2; ++k) {
        int chunk = k * 128 + threadIdx.x;
        int pos = chunk >> 4, off = chunk & 15;
        ((uint4*)(g_wu + ((size_t)(pos * COUT + co)) * CIN))[off] =
            ((const uint4*)&stg[pos][0])[off];
    }
}

// ---------------- kernel 3: x NCHW f32 -> NHWC f16 ----------------
__global__ void __launch_bounds__(256)
transpose_kernel(const float* __restrict__ x) {
    __shared__ __half tile[WIN * 130];
    int b = blockIdx.x / HIN, y = blockIdx.x % HIN;
    const float* src = x + ((size_t)b * CIN) * (HIN * WIN) + y * WIN;
    for (int i = threadIdx.x; i < CIN * WIN; i += 256) {
        int ci = i / WIN, xx = i - ci * WIN;
        tile[xx * 130 + ci] = __float2half_rn(src[(size_t)ci * (HIN * WIN) + xx]);
    }
    __syncthreads();
    __half* dst = g_xh + ((size_t)(b * HIN + y) * WIN) * CIN;
    for (int i = threadIdx.x; i < CIN * WIN; i += 256) {
        int xx = i >> 7, ci = i & 127;
        dst[i] = tile[xx * 130 + ci];
    }
}

// ---------------- kernel 4: input transform, 2-channel vectorized ----------------
__global__ void __launch_bounds__(256)
itrans_kernel() {
    __shared__ __align__(16) __half stg[4][16][128];   // 16 KB
    const int tl  = threadIdx.x >> 6;        // tile slot 0..3
    const int ci2 = threadIdx.x & 63;        // channel pair
    const int tile = blockIdx.x * 4 + tl;
    const int b = tile / TPI;
    const int r = tile - b * TPI;
    const int ty = r / 27, tx = r - ty * 27;
    const __half* src = g_xh
        + ((size_t)((b * HIN + 2 * ty) * WIN + 2 * tx)) * CIN + 2 * ci2;

    float2 d[4][4];
#pragma unroll
    for (int yy = 0; yy < 4; ++yy)
#pragma unroll
        for (int xx = 0; xx < 4; ++xx)
            d[yy][xx] = __half22float2(
                *(const __half2*)(src + (size_t)(yy * WIN + xx) * CIN));
    float2 tm[4][4];
#pragma unroll
    for (int c = 0; c < 4; ++c) {
        tm[0][c] = make_float2(d[0][c].x - d[2][c].x, d[0][c].y - d[2][c].y);
        tm[1][c] = make_float2(d[1][c].x + d[2][c].x, d[1][c].y + d[2][c].y);
        tm[2][c] = make_float2(d[2][c].x - d[1][c].x, d[2][c].y - d[1][c].y);
        tm[3][c] = make_float2(d[1][c].x - d[3][c].x, d[1][c].y - d[3][c].y);
    }
#pragma unroll
    for (int rr = 0; rr < 4; ++rr) {
        float2 v0 = make_float2(tm[rr][0].x - tm[rr][2].x, tm[rr][0].y - tm[rr][2].y);
        float2 v1 = make_float2(tm[rr][1].x + tm[rr][2].x, tm[rr][1].y + tm[rr][2].y);
        float2 v2 = make_float2(tm[rr][2].x - tm[rr][1].x, tm[rr][2].y - tm[rr][1].y);
        float2 v3 = make_float2(tm[rr][1].x - tm[rr][3].x, tm[rr][1].y - tm[rr][3].y);
        __half2* so = (__half2*)&stg[tl][0][2 * ci2];
        so[(rr * 4 + 0) * 64] = __float22half2_rn(v0);
        so[(rr * 4 + 1) * 64] = __float22half2_rn(v1);
        so[(rr * 4 + 2) * 64] = __float22half2_rn(v2);
        so[(rr * 4 + 3) * 64] = __float22half2_rn(v3);
    }
    __syncthreads();
    // contiguous 16 KB block copy (4 tiles consecutive in g_V)
    uint4* dst = (uint4*)(g_V + (size_t)blockIdx.x * 4 * 16 * CIN);
    const uint4* s4 = (const uint4*)&stg[0][0][0];
#pragma unroll
    for (int k = 0; k < 4; ++k)
        dst[k * 256 + threadIdx.x] = s4[k * 256 + threadIdx.x];
}

// ---------------- kernel 5: winograd GEMM, swizzled smem, single-sync windows ----------------
__global__ void __launch_bounds__(512, 1)
wg_gemm_kernel(const float* __restrict__ bias, float* __restrict__ out) {
    extern __shared__ char smem[];
    const uint32_t sb = smem_u32(smem);
    const int tid = threadIdx.x;
    const int wid = tid >> 5, lane = tid & 31;
    const int n0  = blockIdx.x * 128;      // cout base (fast axis -> A L2 reuse)
    const int m0t = blockIdx.y * 64;       // tile base

    // warp grid 2(m) x 8(n); warp tile 32(m) x 16(n)
    const int wm = (wid & 1) * 32;
    const int wn = (wid >> 1) * 16;

    // ---- A producer: thread = (row 0..63, 32B part 0..7), swizzled dst ----
    const int ar = tid >> 3, ap = tid & 7;
    const char* asrcB = (const char*)g_V + (size_t)(m0t + ar) * 4096 + ap * 32;
    const uint32_t arow = sb + (uint32_t)ar * ROWB;
    const uint32_t ac0 = (uint32_t)(((2 * ap)     ^ (ar & 7)) << 4);
    const uint32_t ac1 = (uint32_t)(((2 * ap + 1) ^ (ar & 7)) << 4);

    // ---- B producer: thread = (row 0..127, 64B part 0..3), swizzled dst ----
    const int br = tid >> 2, bp = tid & 3;
    const char* bsrcB = (const char*)g_wu + (size_t)(n0 + br) * 256 + bp * 64;
    const uint32_t brow = sb + A_SM + (uint32_t)br * ROWB;
    uint32_t bc[4];
#pragma unroll
    for (int j = 0; j < 4; ++j)
        bc[j] = (uint32_t)(((4 * bp + j) ^ (br & 7)) << 4);

    // ---- ldmatrix bases (swizzle applied per ks) ----
    uint32_t abase[2], as7[2];
#pragma unroll
    for (int mf = 0; mf < 2; ++mf) {
        const int r = wm + mf * 16 + (lane & 15);
        abase[mf] = sb + (uint32_t)r * ROWB;
        as7[mf]   = (uint32_t)(r & 7);
    }
    const uint32_t ahi = (uint32_t)(lane >> 4);
    const int rb = wn + ((lane >> 4) << 3) + (lane & 7);
    const uint32_t bbase = sb + A_SM + (uint32_t)rb * ROWB;
    const uint32_t bs7   = (uint32_t)(rb & 7);
    const uint32_t bhi   = (uint32_t)((lane >> 3) & 1);

    // persistent winograd-output accumulators
    float oacc[2][2][4][4];
#pragma unroll
    for (int mf = 0; mf < 2; ++mf)
#pragma unroll
        for (int nf = 0; nf < 2; ++nf)
#pragma unroll
            for (int e = 0; e < 4; ++e)
#pragma unroll
                for (int o = 0; o < 4; ++o) oacc[mf][nf][e][o] = 0.f;

    // prefetch pos 0 into stage 0
    {
        cpa16(arow + ac0, asrcB);
        cpa16(arow + ac1, asrcB + 16);
#pragma unroll
        for (int j = 0; j < 4; ++j) cpa16(brow + bc[j], bsrcB + j * 16);
        cpa_commit();
    }

#pragma unroll
    for (int pos = 0; pos < 16; ++pos) {
        cpa_wait<0>();                // pos's data complete (sole group in flight)
        __syncthreads();              // visibility + stage-overwrite safety
        if (pos + 1 < 16) {           // prefetch pos+1; completes during compute
            const char* as = asrcB + (pos + 1) * 256;
            const char* bs = bsrcB + (size_t)(pos + 1) * (COUT * 256);
            const uint32_t so = (uint32_t)((pos + 1) & 1) * STG;
            cpa16(arow + so + ac0, as);
            cpa16(arow + so + ac1, as + 16);
#pragma unroll
            for (int j = 0; j < 4; ++j) cpa16(brow + so + bc[j], bs + j * 16);
            cpa_commit();
        }

        const uint32_t soff = (uint32_t)(pos & 1) * STG;

        float facc[2][2][4];
#pragma unroll
        for (int mf = 0; mf < 2; ++mf)
#pragma unroll
            for (int nf = 0; nf < 2; ++nf)
#pragma unroll
                for (int e = 0; e < 4; ++e) facc[mf][nf][e] = 0.f;

#pragma unroll
        for (int ks = 0; ks < 8; ++ks) {
            uint32_t afr[2][4], bfr[4];
            const uint32_t kc = (uint32_t)(ks << 1);
            ldsm4(afr[0], abase[0] + soff + (((kc | ahi) ^ as7[0]) << 4));
            ldsm4(afr[1], abase[1] + soff + (((kc | ahi) ^ as7[1]) << 4));
            ldsm4(bfr,    bbase    + soff + (((kc | bhi) ^ bs7)    << 4));
            mma16816(facc[0][0], afr[0], bfr);
            mma16816(facc[0][1], afr[0], bfr + 2);
            mma16816(facc[1][0], afr[1], bfr);
            mma16816(facc[1][1], afr[1], bfr + 2);
        }

        // compile-time output-transform coefficients: w in {0, +1, -1}
        const int p = pos >> 2, q = pos & 3;
        const float cp0 = (p == 3) ? 0.f : 1.f;
        const float cp1 = (p == 0) ? 0.f : ((p == 1) ? 1.f : -1.f);
        const float cq0 = (q == 3) ? 0.f : 1.f;
        const float cq1 = (q == 0) ? 0.f : ((q == 1) ? 1.f : -1.f);
        const float w00 = cp0 * cq0, w01 = cp0 * cq1;
        const float w10 = cp1 * cq0, w11 = cp1 * cq1;
#pragma unroll
        for (int mf = 0; mf < 2; ++mf)
#pragma unroll
            for (int nf = 0; nf < 2; ++nf)
#pragma unroll
                for (int e = 0; e < 4; ++e) {
                    const float f = facc[mf][nf][e];
                    if (w00 != 0.f) oacc[mf][nf][e][0] += w00 * f;
                    if (w01 != 0.f) oacc[mf][nf][e][1] += w01 * f;
                    if (w10 != 0.f) oacc[mf][nf][e][2] += w10 * f;
                    if (w11 != 0.f) oacc[mf][nf][e][3] += w11 * f;
                }
    }
    __syncthreads();                  // mainloop smem reads done

    // stage 2x2 outputs: ep4[co][tile] with padded stride EPS
    float4* ep4 = (float4*)smem;      // 128*65*16 = 133120
    {
        const int quad = lane >> 2, tq = lane & 3;
#pragma unroll
        for (int mf = 0; mf < 2; ++mf)
#pragma unroll
            for (int nf = 0; nf < 2; ++nf)
#pragma unroll
                for (int e = 0; e < 4; ++e) {
                    const int m_l  = wm + mf * 16 + quad + 8 * (e >> 1);
                    const int co_l = wn + nf * 8 + tq * 2 + (e & 1);
                    ep4[co_l * EPS + m_l] = make_float4(
                        oacc[mf][nf][e][0], oacc[mf][nf][e][1],
                        oacc[mf][nf][e][2], oacc[mf][nf][e][3]);
                }
    }
    __syncthreads();

    // writer: 2x2 pixels per (tile, co), + bias
    {
        const int m = tid & 63, grp = tid >> 6;   // 8 groups x 16 co
        const int tg = m0t + m;
        const int b = tg / TPI;
        const int rr = tg - b * TPI;
        const int ty = rr / 27, tx = rr - ty * 27;
        float* ob = out + (size_t)b * COUT * NPIX + (2 * ty) * WOUT + 2 * tx;
#pragma unroll
        for (int cc = 0; cc < 16; ++cc) {
            const int co_l = grp * 16 + cc;
            float4 v = ep4[co_l * EPS + m];
            const float bv = __ldg(bias + n0 + co_l);
            float* pp = ob + (size_t)(n0 + co_l) * NPIX;
            *(float2*)pp          = make_float2(v.x + bv, v.y + bv);
            *(float2*)(pp + WOUT) = make_float2(v.z + bv, v.w + bv);
        }
    }
}

// ---------------- launch ----------------
extern "C" void kernel_launch(void* const* d_in, const int* in_sizes, int n_in,
                              void* d_out, int out_size) {
    const float* x    = (const float*)d_in[0];
    const float* w    = (const float*)d_in[1];
    const float* bias = (const float*)d_in[2];
    const float* wp   = (const float*)d_in[3];
    const float* wn   = (const float*)d_in[4];
    float* out = (float*)d_out;

    maxabs_kernel<<<256, 256>>>(w, NW);
    wtrans_kernel<<<COUT, 128>>>(w, wp, wn);
    transpose_kernel<<<BATCH * HIN, 256>>>(x);
    itrans_kernel<<<NTILES / 4, 256>>>();

    cudaFuncSetAttribute(wg_gemm_kernel,
                         cudaFuncAttributeMaxDynamicSharedMemorySize, SM_TOTAL);
    dim3 grid(COUT / 128, NTILES / 64);   // 2 x 729 (co fast -> A L2 reuse)
    wg_gemm_kernel<<<grid, 512, SM_TOTAL>>>(bias, out);
}